// round 9
// baseline (speedup 1.0000x reference)
#include <cuda_runtime.h>
#include <stdint.h>

// LSTM, B=4096, T=2048, I=1, H=10.
// Round 9: R8's warp layout (3 single batches/warp, 10 lanes each, 1366 warps)
// + GATE-DIMENSION f32x2 packing: gates (i,f) and (g,o) share one packed
// 11-deep fma.rn.f32x2 chain each -> matvec 44 FFMA -> 22 FFMA2. Exact fp32.
// h is exchanged duplicated ({h,h} u64 in smem) so packed multiplies need no
// per-step duplication. sigmoid = 0.5*tanh(a/2)+0.5 folded into weights,
// h stored as h'=2h.

#define FULL_MASK 0xFFFFFFFFu

constexpr int Bv = 4096;
constexpr int Tv = 2048;
constexpr int Hv = 10;
constexpr int BATCH_PER_WARP = 3;
constexpr int WARPS_PER_BLOCK = 10;
constexpr int NBLOCKS = 148;                   // 1480 warps launched, 1366 live
constexpr int THREADS = WARPS_PER_BLOCK * 32;  // 320

__device__ __forceinline__ unsigned long long pack2(float lo, float hi) {
    unsigned long long r;
    asm("mov.b64 %0, {%1, %2};" : "=l"(r) : "f"(lo), "f"(hi));
    return r;
}
__device__ __forceinline__ void unpack2(unsigned long long v, float& lo, float& hi) {
    asm("mov.b64 {%0, %1}, %2;" : "=f"(lo), "=f"(hi) : "l"(v));
}
__device__ __forceinline__ unsigned long long fma2(unsigned long long a,
                                                   unsigned long long b,
                                                   unsigned long long c) {
    unsigned long long d;
    asm("fma.rn.f32x2 %0, %1, %2, %3;" : "=l"(d) : "l"(a), "l"(b), "l"(c));
    return d;
}
__device__ __forceinline__ float tanh_a(float x) {
    float r; asm("tanh.approx.f32 %0, %1;" : "=f"(r) : "f"(x)); return r;
}

__global__ void __launch_bounds__(THREADS, 1)
lstm_kernel(const float* __restrict__ x,
            const float* __restrict__ W_ih,   // [40,1]
            const float* __restrict__ W_hh,   // [40,10]
            const float* __restrict__ b_ih,   // [40]
            const float* __restrict__ b_hh,   // [40]
            const float* __restrict__ W_out,  // [1,10]
            const float* __restrict__ b_out,  // [1]
            float* __restrict__ out)          // [4096]
{
    // h exchange, duplicated form: hbuf[..][j] = {h'[j], h'[j]} (u64).
    // 12-u64 stride (96B) keeps the 5 LDS.128 16B-aligned, conflict-free.
    __shared__ __align__(16) unsigned long long hbuf[2][WARPS_PER_BLOCK][4][12];

    const int warp = threadIdx.x >> 5;
    const int lane = threadIdx.x & 31;
    const int gw   = blockIdx.x * WARPS_PER_BLOCK + warp;
    if (gw * BATCH_PER_WARP >= Bv) return;     // whole-warp exit

    const int g    = lane / 10;                // 0..2 batches, 3 = idle lanes
    const int j    = lane - g * 10;            // hidden unit owned by this lane
    const int base = g * 10;
    const int batch = gw * BATCH_PER_WARP + g;
    const bool active = (g < 3) && (batch < Bv);
    const int b = active ? batch : 0;          // clamp for safe loads

    // ---- Packed per-lane weights. Halves: lo = first gate, hi = second.
    // Pair (i,f): both sigmoid -> gate scale 0.5; pair (g,o): g tanh (1.0),
    // o sigmoid (0.5). h stored as h'=2h -> W_hh rows get an extra 0.5.
    unsigned long long wif[10], wgo[10], bif, bgo, wihif, wihgo;
    {
        const int ri = 0 * 10 + j, rf = 1 * 10 + j, rg = 2 * 10 + j, ro = 3 * 10 + j;
        bif = pack2((b_ih[ri] + b_hh[ri]) * 0.5f, (b_ih[rf] + b_hh[rf]) * 0.5f);
        bgo = pack2((b_ih[rg] + b_hh[rg]) * 1.0f, (b_ih[ro] + b_hh[ro]) * 0.5f);
        wihif = pack2(W_ih[ri] * 0.5f, W_ih[rf] * 0.5f);
        wihgo = pack2(W_ih[rg] * 1.0f, W_ih[ro] * 0.5f);
#pragma unroll
        for (int k = 0; k < 10; k++) {
            wif[k] = pack2(W_hh[ri * Hv + k] * 0.25f, W_hh[rf * Hv + k] * 0.25f);
            wgo[k] = pack2(W_hh[rg * Hv + k] * 0.5f,  W_hh[ro * Hv + k] * 0.25f);
        }
    }

    // ---- State: duplicated packed h' ({h,h}), scalar c.
    unsigned long long h2d[10];
#pragma unroll
    for (int k = 0; k < 10; k++) h2d[k] = 0ull;
    float c = 0.f, hown = 0.f;                 // hown = h' of own unit

    unsigned long long* st0 = &hbuf[0][warp][g][j];
    unsigned long long* st1 = &hbuf[1][warp][g][j];
    const ulonglong2* grp0 = reinterpret_cast<const ulonglong2*>(&hbuf[0][warp][g][0]);
    const ulonglong2* grp1 = reinterpret_cast<const ulonglong2*>(&hbuf[1][warp][g][0]);

    const float4* x4 = reinterpret_cast<const float4*>(x + (size_t)b * Tv);
    float4 nx = x4[0];                         // double-buffered x (4 steps/load)

    for (int t0 = 0; t0 < Tv; t0 += 4) {
        const float4 cur = nx;
        const int nxt = (t0 >> 2) + 1;
        if (nxt < Tv / 4) nx = x4[nxt];

#pragma unroll
        for (int u = 0; u < 4; u++) {
            const float xt = (u == 0) ? cur.x : (u == 1) ? cur.y : (u == 2) ? cur.z : cur.w;
            const unsigned long long x2 = pack2(xt, xt);

            // 2 packed 11-deep chains: (i,f) and (g,o).
            unsigned long long aif = fma2(x2, wihif, bif);
            unsigned long long ago = fma2(x2, wihgo, bgo);
#pragma unroll
            for (int k = 0; k < 10; k++) {
                aif = fma2(h2d[k], wif[k], aif);
                ago = fma2(h2d[k], wgo[k], ago);
            }

            float ai, af, ag, ao;
            unpack2(ago, ag, ao);              // g first (c-critical)
            unpack2(aif, ai, af);

            const float tg = tanh_a(ag);
            const float ti = tanh_a(ai);
            const float tf = tanh_a(af);
            const float to = tanh_a(ao);

            const float iv = fmaf(0.5f, ti, 0.5f);
            const float fv = fmaf(0.5f, tf, 0.5f);
            c = fmaf(fv, c, iv * tg);
            const float tc = tanh_a(c);
            hown = fmaf(to, tc, tc);           // h' = 2h

            // Broadcast duplicated h' through smem (parity double-buffered).
            const unsigned long long hd = pack2(hown, hown);
            if ((u & 1) == 0) {
                *st0 = hd;
                __syncwarp();
#pragma unroll
                for (int m = 0; m < 5; m++) {
                    const ulonglong2 v = grp0[m];
                    h2d[2 * m] = v.x;
                    h2d[2 * m + 1] = v.y;
                }
            } else {
                *st1 = hd;
                __syncwarp();
#pragma unroll
                for (int m = 0; m < 5; m++) {
                    const ulonglong2 v = grp1[m];
                    h2d[2 * m] = v.x;
                    h2d[2 * m + 1] = v.y;
                }
            }
        }
    }

    // ---- Epilogue: out[b] = h . W_out + b_out, with h = 0.5*h'.
    const float p = hown * (W_out[j] * 0.5f);
    float sum = 0.f;
#pragma unroll
    for (int k = 0; k < 10; k++) {
        sum += __shfl_sync(FULL_MASK, p, base + k);
    }
    if (active && j == 0) {
        out[b] = sum + b_out[0];
    }
}

extern "C" void kernel_launch(void* const* d_in, const int* in_sizes, int n_in,
                              void* d_out, int out_size) {
    (void)in_sizes; (void)n_in; (void)out_size;
    const float* x     = (const float*)d_in[0];
    const float* W_ih  = (const float*)d_in[1];
    const float* W_hh  = (const float*)d_in[2];
    const float* b_ih  = (const float*)d_in[3];
    const float* b_hh  = (const float*)d_in[4];
    const float* W_out = (const float*)d_in[5];
    const float* b_out = (const float*)d_in[6];
    float* out = (float*)d_out;

    lstm_kernel<<<NBLOCKS, THREADS>>>(x, W_ih, W_hh, b_ih, b_hh, W_out, b_out, out);
}

// round 10
// speedup vs baseline: 1.1741x; 1.1741x over previous
#include <cuda_runtime.h>
#include <cuda_fp16.h>
#include <stdint.h>

// LSTM, B=4096, T=2048, I=1, H=10.
// Round 10: R8 layout (3 single batches/warp, 10 lanes each, 1366 warps) with
// the recurrent matvec in packed fp16 (fma.rn.f16x2, true 2x FMA-pipe
// throughput; f32x2 was measured as 0x in R9). Gate pairs (i,f),(g,o) share
// one 11-deep f16x2 chain each; gates activated by tanh.approx.f16x2.
// c accumulator and the c-update path stay fp32. sigmoid = 0.5*tanh(a/2)+0.5
// folded into weights; h stored as h'=2h (extra 0.5 on W_hh rows).

#define FULL_MASK 0xFFFFFFFFu

constexpr int Bv = 4096;
constexpr int Tv = 2048;
constexpr int Hv = 10;
constexpr int BATCH_PER_WARP = 3;
constexpr int WARPS_PER_BLOCK = 10;
constexpr int NBLOCKS = 148;                   // 1480 warps launched, 1366 live
constexpr int THREADS = WARPS_PER_BLOCK * 32;  // 320

// d = {lo, hi} as f16x2 from two fp32 (one F2FP.PACK).
__device__ __forceinline__ uint32_t pack_h2(float lo, float hi) {
    uint32_t d;
    asm("cvt.rn.f16x2.f32 %0, %1, %2;" : "=r"(d) : "f"(hi), "f"(lo));
    return d;
}
__device__ __forceinline__ void unpack_h2(uint32_t v, float& lo, float& hi) {
    asm("{\n\t"
        ".reg .b16 l, h;\n\t"
        "mov.b32 {l, h}, %2;\n\t"
        "cvt.f32.f16 %0, l;\n\t"
        "cvt.f32.f16 %1, h;\n\t"
        "}" : "=f"(lo), "=f"(hi) : "r"(v));
}
__device__ __forceinline__ uint32_t hfma2(uint32_t a, uint32_t b, uint32_t c) {
    uint32_t d;
    asm("fma.rn.f16x2 %0, %1, %2, %3;" : "=r"(d) : "r"(a), "r"(b), "r"(c));
    return d;
}
__device__ __forceinline__ uint32_t tanh2_h(uint32_t a) {
    uint32_t d;
    asm("tanh.approx.f16x2 %0, %1;" : "=r"(d) : "r"(a));
    return d;
}
__device__ __forceinline__ float tanh_a(float x) {
    float r; asm("tanh.approx.f32 %0, %1;" : "=f"(r) : "f"(x)); return r;
}

__global__ void __launch_bounds__(THREADS, 1)
lstm_kernel(const float* __restrict__ x,
            const float* __restrict__ W_ih,   // [40,1]
            const float* __restrict__ W_hh,   // [40,10]
            const float* __restrict__ b_ih,   // [40]
            const float* __restrict__ b_hh,   // [40]
            const float* __restrict__ W_out,  // [1,10]
            const float* __restrict__ b_out,  // [1]
            float* __restrict__ out)          // [4096]
{
    // h exchange, duplicated f16x2: hbuf[..][j] = {h'[j], h'[j]}.
    // 12-u32 stride (48B) keeps the uint4 loads 16B-aligned.
    __shared__ __align__(16) uint32_t hbuf[2][WARPS_PER_BLOCK][4][12];

    const int warp = threadIdx.x >> 5;
    const int lane = threadIdx.x & 31;
    const int gw   = blockIdx.x * WARPS_PER_BLOCK + warp;
    if (gw * BATCH_PER_WARP >= Bv) return;     // whole-warp exit

    const int g    = lane / 10;                // 0..2 batches, 3 = idle lanes
    const int j    = lane - g * 10;            // hidden unit owned by this lane
    const int base = g * 10;
    const int batch = gw * BATCH_PER_WARP + g;
    const bool active = (g < 3) && (batch < Bv);
    const int b = active ? batch : 0;          // clamp for safe loads

    // ---- Weights. Gate scales: i,f,o = 0.5 (sigmoid fold), g = 1.0.
    // h stored as h'=2h -> W_hh rows get an extra 0.5.
    // Recurrent weights as f16x2 pairs: wif={i,f}, wgo={g,o}. Seeds fp32.
    float wih[4], bias[4];
    uint32_t wif16[10], wgo16[10];
    {
        const int ri = 0 * 10 + j, rf = 1 * 10 + j, rg = 2 * 10 + j, ro = 3 * 10 + j;
        bias[0] = (b_ih[ri] + b_hh[ri]) * 0.5f;  wih[0] = W_ih[ri] * 0.5f;
        bias[1] = (b_ih[rf] + b_hh[rf]) * 0.5f;  wih[1] = W_ih[rf] * 0.5f;
        bias[2] = (b_ih[rg] + b_hh[rg]) * 1.0f;  wih[2] = W_ih[rg] * 1.0f;
        bias[3] = (b_ih[ro] + b_hh[ro]) * 0.5f;  wih[3] = W_ih[ro] * 0.5f;
#pragma unroll
        for (int k = 0; k < 10; k++) {
            wif16[k] = pack_h2(W_hh[ri * Hv + k] * 0.25f, W_hh[rf * Hv + k] * 0.25f);
            wgo16[k] = pack_h2(W_hh[rg * Hv + k] * 0.5f,  W_hh[ro * Hv + k] * 0.25f);
        }
    }

    // ---- State: duplicated f16x2 h', fp32 c.
    uint32_t h2d[10];
#pragma unroll
    for (int k = 0; k < 10; k++) h2d[k] = 0u;
    float c = 0.f, hown = 0.f;                 // hown = h' (fp32 master copy)

    uint32_t* st0 = &hbuf[0][warp][g][j];
    uint32_t* st1 = &hbuf[1][warp][g][j];
    const uint4* grp0 = reinterpret_cast<const uint4*>(&hbuf[0][warp][g][0]);
    const uint4* grp1 = reinterpret_cast<const uint4*>(&hbuf[1][warp][g][0]);

    const float4* x4 = reinterpret_cast<const float4*>(x + (size_t)b * Tv);
    float4 nx = x4[0];                         // double-buffered x (4 steps/load)

    for (int t0 = 0; t0 < Tv; t0 += 4) {
        const float4 cur = nx;
        const int nxt = (t0 >> 2) + 1;
        if (nxt < Tv / 4) nx = x4[nxt];

#pragma unroll
        for (int u = 0; u < 4; u++) {
            const float xt = (u == 0) ? cur.x : (u == 1) ? cur.y : (u == 2) ? cur.z : cur.w;

            // fp32 seeds (x*W_ih + b), packed once per gate pair.
            const float si = fmaf(xt, wih[0], bias[0]);
            const float sf = fmaf(xt, wih[1], bias[1]);
            const float sg = fmaf(xt, wih[2], bias[2]);
            const float so = fmaf(xt, wih[3], bias[3]);
            uint32_t aif = pack_h2(si, sf);
            uint32_t ago = pack_h2(sg, so);

            // 2 packed 11-deep f16x2 chains (i,f) and (g,o).
#pragma unroll
            for (int k = 0; k < 10; k++) {
                aif = hfma2(h2d[k], wif16[k], aif);
                ago = hfma2(h2d[k], wgo16[k], ago);
            }

            // Packed fp16 tanh on both pairs (inputs already gate-scaled).
            const uint32_t tgo = tanh2_h(ago);   // {tg, to}
            const uint32_t tif = tanh2_h(aif);   // {ti, tf}

            float tg, to, ti, tf;
            unpack_h2(tgo, tg, to);
            unpack_h2(tif, ti, tf);

            // fp32 c-path: i=0.5ti+0.5, f=0.5tf+0.5, c=f*c+i*g, h'=to*tc+tc.
            const float iv = fmaf(0.5f, ti, 0.5f);
            const float fv = fmaf(0.5f, tf, 0.5f);
            c = fmaf(fv, c, iv * tg);
            const float tc = tanh_a(c);
            hown = fmaf(to, tc, tc);             // h' = 2h

            // Broadcast duplicated {h',h'} f16x2 via smem (parity buffers).
            const uint32_t hd = pack_h2(hown, hown);
            if ((u & 1) == 0) {
                *st0 = hd;
                __syncwarp();
                const uint4 v0 = grp0[0];
                const uint4 v1 = grp0[1];
                const uint2 v2 = reinterpret_cast<const uint2*>(grp0)[4];
                h2d[0] = v0.x; h2d[1] = v0.y; h2d[2] = v0.z; h2d[3] = v0.w;
                h2d[4] = v1.x; h2d[5] = v1.y; h2d[6] = v1.z; h2d[7] = v1.w;
                h2d[8] = v2.x; h2d[9] = v2.y;
            } else {
                *st1 = hd;
                __syncwarp();
                const uint4 v0 = grp1[0];
                const uint4 v1 = grp1[1];
                const uint2 v2 = reinterpret_cast<const uint2*>(grp1)[4];
                h2d[0] = v0.x; h2d[1] = v0.y; h2d[2] = v0.z; h2d[3] = v0.w;
                h2d[4] = v1.x; h2d[5] = v1.y; h2d[6] = v1.z; h2d[7] = v1.w;
                h2d[8] = v2.x; h2d[9] = v2.y;
            }
        }
    }

    // ---- Epilogue: out[b] = h . W_out + b_out, with h = 0.5*h'.
    // hown is the fp32 master copy of this lane's h' (never through fp16).
    const float p = hown * (W_out[j] * 0.5f);
    float sum = 0.f;
#pragma unroll
    for (int k = 0; k < 10; k++) {
        sum += __shfl_sync(FULL_MASK, p, base + k);
    }
    if (active && j == 0) {
        out[b] = sum + b_out[0];
    }
}

extern "C" void kernel_launch(void* const* d_in, const int* in_sizes, int n_in,
                              void* d_out, int out_size) {
    (void)in_sizes; (void)n_in; (void)out_size;
    const float* x     = (const float*)d_in[0];
    const float* W_ih  = (const float*)d_in[1];
    const float* W_hh  = (const float*)d_in[2];
    const float* b_ih  = (const float*)d_in[3];
    const float* b_hh  = (const float*)d_in[4];
    const float* W_out = (const float*)d_in[5];
    const float* b_out = (const float*)d_in[6];
    float* out = (float*)d_out;

    lstm_kernel<<<NBLOCKS, THREADS>>>(x, W_ih, W_hh, b_ih, b_hh, W_out, b_out, out);
}

// round 11
// speedup vs baseline: 1.2224x; 1.0411x over previous
#include <cuda_runtime.h>
#include <cuda_fp16.h>
#include <stdint.h>

// LSTM, B=4096, T=2048, I=1, H=10.
// Round 11: R10 (fp16 gate-pair matvec, fp32 c-path, 3 batches/warp,
// 1366 warps) + (a) fp16 seeds: {x,x} pack + 2 HFMA2 replaces 4 FFMA+2 packs,
// (b) 3-phase stagger so the 3 warps sharing a hot SMSP run ~1/3 step apart.

#define FULL_MASK 0xFFFFFFFFu

constexpr int Bv = 4096;
constexpr int Tv = 2048;
constexpr int Hv = 10;
constexpr int BATCH_PER_WARP = 3;
constexpr int WARPS_PER_BLOCK = 10;
constexpr int NBLOCKS = 148;                   // 1480 warps launched, 1366 live
constexpr int THREADS = WARPS_PER_BLOCK * 32;  // 320

__device__ __forceinline__ uint32_t pack_h2(float lo, float hi) {
    uint32_t d;
    asm("cvt.rn.f16x2.f32 %0, %1, %2;" : "=r"(d) : "f"(hi), "f"(lo));
    return d;
}
__device__ __forceinline__ void unpack_h2(uint32_t v, float& lo, float& hi) {
    asm("{\n\t"
        ".reg .b16 l, h;\n\t"
        "mov.b32 {l, h}, %2;\n\t"
        "cvt.f32.f16 %0, l;\n\t"
        "cvt.f32.f16 %1, h;\n\t"
        "}" : "=f"(lo), "=f"(hi) : "r"(v));
}
__device__ __forceinline__ uint32_t hfma2(uint32_t a, uint32_t b, uint32_t c) {
    uint32_t d;
    asm("fma.rn.f16x2 %0, %1, %2, %3;" : "=r"(d) : "r"(a), "r"(b), "r"(c));
    return d;
}
__device__ __forceinline__ uint32_t tanh2_h(uint32_t a) {
    uint32_t d;
    asm("tanh.approx.f16x2 %0, %1;" : "=r"(d) : "r"(a));
    return d;
}
__device__ __forceinline__ float tanh_a(float x) {
    float r; asm("tanh.approx.f32 %0, %1;" : "=f"(r) : "f"(x)); return r;
}

__global__ void __launch_bounds__(THREADS, 1)
lstm_kernel(const float* __restrict__ x,
            const float* __restrict__ W_ih,   // [40,1]
            const float* __restrict__ W_hh,   // [40,10]
            const float* __restrict__ b_ih,   // [40]
            const float* __restrict__ b_hh,   // [40]
            const float* __restrict__ W_out,  // [1,10]
            const float* __restrict__ b_out,  // [1]
            float* __restrict__ out)          // [4096]
{
    // h exchange, duplicated f16x2: hbuf[..][j] = {h'[j], h'[j]}.
    __shared__ __align__(16) uint32_t hbuf[2][WARPS_PER_BLOCK][4][12];

    const int warp = threadIdx.x >> 5;
    const int lane = threadIdx.x & 31;
    const int gw   = blockIdx.x * WARPS_PER_BLOCK + warp;
    if (gw * BATCH_PER_WARP >= Bv) return;     // whole-warp exit

    const int g    = lane / 10;                // 0..2 batches, 3 = idle lanes
    const int j    = lane - g * 10;            // hidden unit owned by this lane
    const int base = g * 10;
    const int batch = gw * BATCH_PER_WARP + g;
    const bool active = (g < 3) && (batch < Bv);
    const int b = active ? batch : 0;          // clamp for safe loads

    // ---- Weights. Gate scales: i,f,o = 0.5 (sigmoid fold), g = 1.0.
    // h stored as h'=2h -> W_hh rows get an extra 0.5.
    // Everything the matvec touches is f16x2: seeds wih16/bias16, chains w*16.
    uint32_t wih16_if, wih16_go, bias16_if, bias16_go;
    uint32_t wif16[10], wgo16[10];
    {
        const int ri = 0 * 10 + j, rf = 1 * 10 + j, rg = 2 * 10 + j, ro = 3 * 10 + j;
        bias16_if = pack_h2((b_ih[ri] + b_hh[ri]) * 0.5f, (b_ih[rf] + b_hh[rf]) * 0.5f);
        bias16_go = pack_h2((b_ih[rg] + b_hh[rg]) * 1.0f, (b_ih[ro] + b_hh[ro]) * 0.5f);
        wih16_if  = pack_h2(W_ih[ri] * 0.5f, W_ih[rf] * 0.5f);
        wih16_go  = pack_h2(W_ih[rg] * 1.0f, W_ih[ro] * 0.5f);
#pragma unroll
        for (int k = 0; k < 10; k++) {
            wif16[k] = pack_h2(W_hh[ri * Hv + k] * 0.25f, W_hh[rf * Hv + k] * 0.25f);
            wgo16[k] = pack_h2(W_hh[rg * Hv + k] * 0.5f,  W_hh[ro * Hv + k] * 0.25f);
        }
    }

    // ---- State: duplicated f16x2 h', fp32 c.
    uint32_t h2d[10];
#pragma unroll
    for (int k = 0; k < 10; k++) h2d[k] = 0u;
    float c = 0.f, hown = 0.f;                 // hown = h' (fp32 master copy)

    uint32_t* st0 = &hbuf[0][warp][g][j];
    uint32_t* st1 = &hbuf[1][warp][g][j];
    const uint4* grp0 = reinterpret_cast<const uint4*>(&hbuf[0][warp][g][0]);
    const uint4* grp1 = reinterpret_cast<const uint4*>(&hbuf[1][warp][g][0]);

    const float4* x4 = reinterpret_cast<const float4*>(x + (size_t)b * Tv);
    float4 nx = x4[0];                         // double-buffered x (4 steps/load)

    // ---- 3-phase stagger: SMSP slot s = warp&3; warps {s, s+4, s+8} share an
    // SMSP. Delay warp by (warp>>2) * ~1/3 step via a dependent FMA chain.
    {
        const int reps = (warp >> 2) * 20;     // 0 / 20 / 40 dependent FFMA
        float d = 1.0f + (float)lane;
        for (int it = 0; it < reps; it++) d = fmaf(d, 1.0000001f, 1.0f);
        if (d == -1.0f) out[0] = d;            // never true; keeps the chain
    }

    for (int t0 = 0; t0 < Tv; t0 += 4) {
        const float4 cur = nx;
        const int nxt = (t0 >> 2) + 1;
        if (nxt < Tv / 4) nx = x4[nxt];

#pragma unroll
        for (int u = 0; u < 4; u++) {
            const float xt = (u == 0) ? cur.x : (u == 1) ? cur.y : (u == 2) ? cur.z : cur.w;

            // fp16 seeds: one {x,x} pack + two HFMA2.
            const uint32_t xh2 = pack_h2(xt, xt);
            uint32_t aif = hfma2(xh2, wih16_if, bias16_if);
            uint32_t ago = hfma2(xh2, wih16_go, bias16_go);

            // 2 packed 10-deep f16x2 chains (i,f) and (g,o).
#pragma unroll
            for (int k = 0; k < 10; k++) {
                aif = hfma2(h2d[k], wif16[k], aif);
                ago = hfma2(h2d[k], wgo16[k], ago);
            }

            // Packed fp16 tanh on both pairs (inputs already gate-scaled).
            const uint32_t tgo = tanh2_h(ago);   // {tg, to}
            const uint32_t tif = tanh2_h(aif);   // {ti, tf}

            float tg, to, ti, tf;
            unpack_h2(tgo, tg, to);
            unpack_h2(tif, ti, tf);

            // fp32 c-path: i=0.5ti+0.5, f=0.5tf+0.5, c=f*c+i*g, h'=to*tc+tc.
            const float iv = fmaf(0.5f, ti, 0.5f);
            const float fv = fmaf(0.5f, tf, 0.5f);
            c = fmaf(fv, c, iv * tg);
            const float tc = tanh_a(c);
            hown = fmaf(to, tc, tc);             // h' = 2h

            // Broadcast duplicated {h',h'} f16x2 via smem (parity buffers).
            const uint32_t hd = pack_h2(hown, hown);
            if ((u & 1) == 0) {
                *st0 = hd;
                __syncwarp();
                const uint4 v0 = grp0[0];
                const uint4 v1 = grp0[1];
                const uint2 v2 = reinterpret_cast<const uint2*>(grp0)[4];
                h2d[0] = v0.x; h2d[1] = v0.y; h2d[2] = v0.z; h2d[3] = v0.w;
                h2d[4] = v1.x; h2d[5] = v1.y; h2d[6] = v1.z; h2d[7] = v1.w;
                h2d[8] = v2.x; h2d[9] = v2.y;
            } else {
                *st1 = hd;
                __syncwarp();
                const uint4 v0 = grp1[0];
                const uint4 v1 = grp1[1];
                const uint2 v2 = reinterpret_cast<const uint2*>(grp1)[4];
                h2d[0] = v0.x; h2d[1] = v0.y; h2d[2] = v0.z; h2d[3] = v0.w;
                h2d[4] = v1.x; h2d[5] = v1.y; h2d[6] = v1.z; h2d[7] = v1.w;
                h2d[8] = v2.x; h2d[9] = v2.y;
            }
        }
    }

    // ---- Epilogue: out[b] = h . W_out + b_out, with h = 0.5*h'.
    const float p = hown * (W_out[j] * 0.5f);
    float sum = 0.f;
#pragma unroll
    for (int k = 0; k < 10; k++) {
        sum += __shfl_sync(FULL_MASK, p, base + k);
    }
    if (active && j == 0) {
        out[b] = sum + b_out[0];
    }
}

extern "C" void kernel_launch(void* const* d_in, const int* in_sizes, int n_in,
                              void* d_out, int out_size) {
    (void)in_sizes; (void)n_in; (void)out_size;
    const float* x     = (const float*)d_in[0];
    const float* W_ih  = (const float*)d_in[1];
    const float* W_hh  = (const float*)d_in[2];
    const float* b_ih  = (const float*)d_in[3];
    const float* b_hh  = (const float*)d_in[4];
    const float* W_out = (const float*)d_in[5];
    const float* b_out = (const float*)d_in[6];
    float* out = (float*)d_out;

    lstm_kernel<<<NBLOCKS, THREADS>>>(x, W_ih, W_hh, b_ih, b_hh, W_out, b_out, out);
}

// round 12
// speedup vs baseline: 1.2429x; 1.0168x over previous
#include <cuda_runtime.h>
#include <cuda_fp16.h>
#include <stdint.h>

// LSTM, B=4096, T=2048, I=1, H=10.
// Round 12: R11 + packed fp16 c-path front end:
//   s2 = hfma2({.5,.5}, {ti,tf}, {.5,.5}) = {i, f}
//   m2 = hmul2(s2, {tg,to})              = {i*g, f*o(junk)}
// so the scalar fp32 section shrinks to: c = fma(fv, c, ig); tanh; hown.
// Everything else unchanged: fp16 gate-pair matvec (22 HFMA2), fp32 c,
// 3 batches/warp, 1366 warps, smem h-exchange, 3-phase stagger.

#define FULL_MASK 0xFFFFFFFFu

constexpr int Bv = 4096;
constexpr int Tv = 2048;
constexpr int Hv = 10;
constexpr int BATCH_PER_WARP = 3;
constexpr int WARPS_PER_BLOCK = 10;
constexpr int NBLOCKS = 148;                   // 1480 warps launched, 1366 live
constexpr int THREADS = WARPS_PER_BLOCK * 32;  // 320

__device__ __forceinline__ uint32_t pack_h2(float lo, float hi) {
    uint32_t d;
    asm("cvt.rn.f16x2.f32 %0, %1, %2;" : "=r"(d) : "f"(hi), "f"(lo));
    return d;
}
__device__ __forceinline__ float cvt_lo(uint32_t v) {
    float f;
    asm("{ .reg .b16 l, h; mov.b32 {l, h}, %1; cvt.f32.f16 %0, l; }"
        : "=f"(f) : "r"(v));
    return f;
}
__device__ __forceinline__ float cvt_hi(uint32_t v) {
    float f;
    asm("{ .reg .b16 l, h; mov.b32 {l, h}, %1; cvt.f32.f16 %0, h; }"
        : "=f"(f) : "r"(v));
    return f;
}
__device__ __forceinline__ uint32_t hfma2(uint32_t a, uint32_t b, uint32_t c) {
    uint32_t d;
    asm("fma.rn.f16x2 %0, %1, %2, %3;" : "=r"(d) : "r"(a), "r"(b), "r"(c));
    return d;
}
__device__ __forceinline__ uint32_t hmul2(uint32_t a, uint32_t b) {
    uint32_t d;
    asm("mul.rn.f16x2 %0, %1, %2;" : "=r"(d) : "r"(a), "r"(b));
    return d;
}
__device__ __forceinline__ uint32_t tanh2_h(uint32_t a) {
    uint32_t d;
    asm("tanh.approx.f16x2 %0, %1;" : "=r"(d) : "r"(a));
    return d;
}
__device__ __forceinline__ float tanh_a(float x) {
    float r; asm("tanh.approx.f32 %0, %1;" : "=f"(r) : "f"(x)); return r;
}

__global__ void __launch_bounds__(THREADS, 1)
lstm_kernel(const float* __restrict__ x,
            const float* __restrict__ W_ih,   // [40,1]
            const float* __restrict__ W_hh,   // [40,10]
            const float* __restrict__ b_ih,   // [40]
            const float* __restrict__ b_hh,   // [40]
            const float* __restrict__ W_out,  // [1,10]
            const float* __restrict__ b_out,  // [1]
            float* __restrict__ out)          // [4096]
{
    // h exchange, duplicated f16x2: hbuf[..][j] = {h'[j], h'[j]}.
    __shared__ __align__(16) uint32_t hbuf[2][WARPS_PER_BLOCK][4][12];

    const int warp = threadIdx.x >> 5;
    const int lane = threadIdx.x & 31;
    const int gw   = blockIdx.x * WARPS_PER_BLOCK + warp;
    if (gw * BATCH_PER_WARP >= Bv) return;     // whole-warp exit

    const int g    = lane / 10;                // 0..2 batches, 3 = idle lanes
    const int j    = lane - g * 10;            // hidden unit owned by this lane
    const int base = g * 10;
    const int batch = gw * BATCH_PER_WARP + g;
    const bool active = (g < 3) && (batch < Bv);
    const int b = active ? batch : 0;          // clamp for safe loads

    // ---- Weights. Gate scales: i,f,o = 0.5 (sigmoid fold), g = 1.0.
    // h stored as h'=2h -> W_hh rows get an extra 0.5. All matvec data f16x2.
    uint32_t wih16_if, wih16_go, bias16_if, bias16_go;
    uint32_t wif16[10], wgo16[10];
    {
        const int ri = 0 * 10 + j, rf = 1 * 10 + j, rg = 2 * 10 + j, ro = 3 * 10 + j;
        bias16_if = pack_h2((b_ih[ri] + b_hh[ri]) * 0.5f, (b_ih[rf] + b_hh[rf]) * 0.5f);
        bias16_go = pack_h2((b_ih[rg] + b_hh[rg]) * 1.0f, (b_ih[ro] + b_hh[ro]) * 0.5f);
        wih16_if  = pack_h2(W_ih[ri] * 0.5f, W_ih[rf] * 0.5f);
        wih16_go  = pack_h2(W_ih[rg] * 1.0f, W_ih[ro] * 0.5f);
#pragma unroll
        for (int k = 0; k < 10; k++) {
            wif16[k] = pack_h2(W_hh[ri * Hv + k] * 0.25f, W_hh[rf * Hv + k] * 0.25f);
            wgo16[k] = pack_h2(W_hh[rg * Hv + k] * 0.5f,  W_hh[ro * Hv + k] * 0.25f);
        }
    }
    const uint32_t half2_16 = pack_h2(0.5f, 0.5f);

    // ---- State: duplicated f16x2 h', fp32 c.
    uint32_t h2d[10];
#pragma unroll
    for (int k = 0; k < 10; k++) h2d[k] = 0u;
    float c = 0.f, hown = 0.f;                 // hown = h' (fp32 master copy)

    uint32_t* st0 = &hbuf[0][warp][g][j];
    uint32_t* st1 = &hbuf[1][warp][g][j];
    const uint4* grp0 = reinterpret_cast<const uint4*>(&hbuf[0][warp][g][0]);
    const uint4* grp1 = reinterpret_cast<const uint4*>(&hbuf[1][warp][g][0]);

    const float4* x4 = reinterpret_cast<const float4*>(x + (size_t)b * Tv);
    float4 nx = x4[0];                         // double-buffered x (4 steps/load)

    // ---- 3-phase stagger: warps {s, s+4, s+8} share an SMSP; delay by
    // (warp>>2) * ~1/3 step via a dependent FMA chain.
    {
        const int reps = (warp >> 2) * 20;     // 0 / 20 / 40 dependent FFMA
        float d = 1.0f + (float)lane;
        for (int it = 0; it < reps; it++) d = fmaf(d, 1.0000001f, 1.0f);
        if (d == -1.0f) out[0] = d;            // never true; keeps the chain
    }

    for (int t0 = 0; t0 < Tv; t0 += 4) {
        const float4 cur = nx;
        const int nxt = (t0 >> 2) + 1;
        if (nxt < Tv / 4) nx = x4[nxt];

#pragma unroll
        for (int u = 0; u < 4; u++) {
            const float xt = (u == 0) ? cur.x : (u == 1) ? cur.y : (u == 2) ? cur.z : cur.w;

            // fp16 seeds: one {x,x} pack + two HFMA2.
            const uint32_t xh2 = pack_h2(xt, xt);
            uint32_t aif = hfma2(xh2, wih16_if, bias16_if);
            uint32_t ago = hfma2(xh2, wih16_go, bias16_go);

            // 2 packed 10-deep f16x2 chains (i,f) and (g,o).
#pragma unroll
            for (int k = 0; k < 10; k++) {
                aif = hfma2(h2d[k], wif16[k], aif);
                ago = hfma2(h2d[k], wgo16[k], ago);
            }

            // Packed activations + packed c-path front end.
            const uint32_t tif = tanh2_h(aif);   // {ti, tf}
            const uint32_t tgo = tanh2_h(ago);   // {tg, to}
            const uint32_t s2  = hfma2(half2_16, tif, half2_16); // {i, f}
            const uint32_t m2  = hmul2(s2, tgo);                 // {i*g, f*o junk}

            const float ig = cvt_lo(m2);
            const float fv = cvt_hi(s2);
            const float to = cvt_hi(tgo);

            // fp32 tail: c = f*c + i*g, h' = to*tc + tc.
            c = fmaf(fv, c, ig);
            const float tc = tanh_a(c);
            hown = fmaf(to, tc, tc);             // h' = 2h

            // Broadcast duplicated {h',h'} f16x2 via smem (parity buffers).
            const uint32_t hd = pack_h2(hown, hown);
            if ((u & 1) == 0) {
                *st0 = hd;
                __syncwarp();
                const uint4 v0 = grp0[0];
                const uint4 v1 = grp0[1];
                const uint2 v2 = reinterpret_cast<const uint2*>(grp0)[4];
                h2d[0] = v0.x; h2d[1] = v0.y; h2d[2] = v0.z; h2d[3] = v0.w;
                h2d[4] = v1.x; h2d[5] = v1.y; h2d[6] = v1.z; h2d[7] = v1.w;
                h2d[8] = v2.x; h2d[9] = v2.y;
            } else {
                *st1 = hd;
                __syncwarp();
                const uint4 v0 = grp1[0];
                const uint4 v1 = grp1[1];
                const uint2 v2 = reinterpret_cast<const uint2*>(grp1)[4];
                h2d[0] = v0.x; h2d[1] = v0.y; h2d[2] = v0.z; h2d[3] = v0.w;
                h2d[4] = v1.x; h2d[5] = v1.y; h2d[6] = v1.z; h2d[7] = v1.w;
                h2d[8] = v2.x; h2d[9] = v2.y;
            }
        }
    }

    // ---- Epilogue: out[b] = h . W_out + b_out, with h = 0.5*h'.
    const float p = hown * (W_out[j] * 0.5f);
    float sum = 0.f;
#pragma unroll
    for (int k = 0; k < 10; k++) {
        sum += __shfl_sync(FULL_MASK, p, base + k);
    }
    if (active && j == 0) {
        out[b] = sum + b_out[0];
    }
}

extern "C" void kernel_launch(void* const* d_in, const int* in_sizes, int n_in,
                              void* d_out, int out_size) {
    (void)in_sizes; (void)n_in; (void)out_size;
    const float* x     = (const float*)d_in[0];
    const float* W_ih  = (const float*)d_in[1];
    const float* W_hh  = (const float*)d_in[2];
    const float* b_ih  = (const float*)d_in[3];
    const float* b_hh  = (const float*)d_in[4];
    const float* W_out = (const float*)d_in[5];
    const float* b_out = (const float*)d_in[6];
    float* out = (float*)d_out;

    lstm_kernel<<<NBLOCKS, THREADS>>>(x, W_ih, W_hh, b_ih, b_hh, W_out, b_out, out);
}

// round 13
// speedup vs baseline: 1.2524x; 1.0077x over previous
#include <cuda_runtime.h>
#include <cuda_fp16.h>
#include <stdint.h>

// LSTM, B=4096, T=2048, I=1, H=10.
// Round 13: R12 + (a) NO syncwarp in the exchange: the warp is fully
// convergent, so STS -> later LDS are ordered by the per-warp in-order LSU;
// compiler ordering enforced via asm volatile + memory clobber.
// (b) software-pipelined seeds: next step's x-dependent seed HFMA2s execute
// inside the STS->LDS window. Everything else as R12: fp16 gate-pair matvec,
// packed fp16 activations/c-front, fp32 c, 3 batches/warp, 1366 warps.

#define FULL_MASK 0xFFFFFFFFu

constexpr int Bv = 4096;
constexpr int Tv = 2048;
constexpr int Hv = 10;
constexpr int BATCH_PER_WARP = 3;
constexpr int WARPS_PER_BLOCK = 10;
constexpr int NBLOCKS = 148;                   // 1480 warps launched, 1366 live
constexpr int THREADS = WARPS_PER_BLOCK * 32;  // 320

__device__ __forceinline__ uint32_t smem_u32(const void* p) {
    uint32_t a;
    asm("{ .reg .u64 t; cvta.to.shared.u64 t, %1; cvt.u32.u64 %0, t; }"
        : "=r"(a) : "l"(p));
    return a;
}
__device__ __forceinline__ uint32_t pack_h2(float lo, float hi) {
    uint32_t d;
    asm("cvt.rn.f16x2.f32 %0, %1, %2;" : "=r"(d) : "f"(hi), "f"(lo));
    return d;
}
__device__ __forceinline__ float cvt_lo(uint32_t v) {
    float f;
    asm("{ .reg .b16 l, h; mov.b32 {l, h}, %1; cvt.f32.f16 %0, l; }"
        : "=f"(f) : "r"(v));
    return f;
}
__device__ __forceinline__ float cvt_hi(uint32_t v) {
    float f;
    asm("{ .reg .b16 l, h; mov.b32 {l, h}, %1; cvt.f32.f16 %0, h; }"
        : "=f"(f) : "r"(v));
    return f;
}
__device__ __forceinline__ uint32_t hfma2(uint32_t a, uint32_t b, uint32_t c) {
    uint32_t d;
    asm("fma.rn.f16x2 %0, %1, %2, %3;" : "=r"(d) : "r"(a), "r"(b), "r"(c));
    return d;
}
__device__ __forceinline__ uint32_t hmul2(uint32_t a, uint32_t b) {
    uint32_t d;
    asm("mul.rn.f16x2 %0, %1, %2;" : "=r"(d) : "r"(a), "r"(b));
    return d;
}
__device__ __forceinline__ uint32_t tanh2_h(uint32_t a) {
    uint32_t d;
    asm("tanh.approx.f16x2 %0, %1;" : "=r"(d) : "r"(a));
    return d;
}
__device__ __forceinline__ float tanh_a(float x) {
    float r; asm("tanh.approx.f32 %0, %1;" : "=f"(r) : "f"(x)); return r;
}

// Ordered smem ops (compiler barriers; HW order guaranteed by per-warp
// in-order LSU for a convergent warp).
__device__ __forceinline__ void sts32(uint32_t addr, uint32_t v) {
    asm volatile("st.shared.b32 [%0], %1;" :: "r"(addr), "r"(v) : "memory");
}
__device__ __forceinline__ void lds128(uint32_t addr, uint32_t& a, uint32_t& b,
                                       uint32_t& c, uint32_t& d) {
    asm volatile("ld.shared.v4.b32 {%0, %1, %2, %3}, [%4];"
                 : "=r"(a), "=r"(b), "=r"(c), "=r"(d) : "r"(addr) : "memory");
}
__device__ __forceinline__ void lds64(uint32_t addr, uint32_t& a, uint32_t& b) {
    asm volatile("ld.shared.v2.b32 {%0, %1}, [%2];"
                 : "=r"(a), "=r"(b) : "r"(addr) : "memory");
}

__global__ void __launch_bounds__(THREADS, 1)
lstm_kernel(const float* __restrict__ x,
            const float* __restrict__ W_ih,   // [40,1]
            const float* __restrict__ W_hh,   // [40,10]
            const float* __restrict__ b_ih,   // [40]
            const float* __restrict__ b_hh,   // [40]
            const float* __restrict__ W_out,  // [1,10]
            const float* __restrict__ b_out,  // [1]
            float* __restrict__ out)          // [4096]
{
    // h exchange, duplicated f16x2: hbuf[..][j] = {h'[j], h'[j]}.
    __shared__ __align__(16) uint32_t hbuf[2][WARPS_PER_BLOCK][4][12];

    const int warp = threadIdx.x >> 5;
    const int lane = threadIdx.x & 31;
    const int gw   = blockIdx.x * WARPS_PER_BLOCK + warp;
    if (gw * BATCH_PER_WARP >= Bv) return;     // whole-warp exit

    const int g    = lane / 10;                // 0..2 batches, 3 = idle lanes
    const int j    = lane - g * 10;            // hidden unit owned by this lane
    const int base = g * 10;
    const int batch = gw * BATCH_PER_WARP + g;
    const bool active = (g < 3) && (batch < Bv);
    const int b = active ? batch : 0;          // clamp for safe loads

    // ---- Weights. Gate scales: i,f,o = 0.5 (sigmoid fold), g = 1.0.
    // h stored as h'=2h -> W_hh rows get an extra 0.5. All matvec data f16x2.
    uint32_t wih16_if, wih16_go, bias16_if, bias16_go;
    uint32_t wif16[10], wgo16[10];
    {
        const int ri = 0 * 10 + j, rf = 1 * 10 + j, rg = 2 * 10 + j, ro = 3 * 10 + j;
        bias16_if = pack_h2((b_ih[ri] + b_hh[ri]) * 0.5f, (b_ih[rf] + b_hh[rf]) * 0.5f);
        bias16_go = pack_h2((b_ih[rg] + b_hh[rg]) * 1.0f, (b_ih[ro] + b_hh[ro]) * 0.5f);
        wih16_if  = pack_h2(W_ih[ri] * 0.5f, W_ih[rf] * 0.5f);
        wih16_go  = pack_h2(W_ih[rg] * 1.0f, W_ih[ro] * 0.5f);
#pragma unroll
        for (int k = 0; k < 10; k++) {
            wif16[k] = pack_h2(W_hh[ri * Hv + k] * 0.25f, W_hh[rf * Hv + k] * 0.25f);
            wgo16[k] = pack_h2(W_hh[rg * Hv + k] * 0.5f,  W_hh[ro * Hv + k] * 0.25f);
        }
    }
    const uint32_t half2_16 = pack_h2(0.5f, 0.5f);

    // ---- State: duplicated f16x2 h', fp32 c.
    uint32_t h2d[10];
#pragma unroll
    for (int k = 0; k < 10; k++) h2d[k] = 0u;
    float c = 0.f, hown = 0.f;                 // hown = h' (fp32 master copy)

    uint32_t st_addr[2], ld_addr[2];
    {
        const uint32_t b0 = smem_u32(&hbuf[0][warp][g][0]);
        const uint32_t b1 = smem_u32(&hbuf[1][warp][g][0]);
        st_addr[0] = b0 + 4u * (uint32_t)j;
        st_addr[1] = b1 + 4u * (uint32_t)j;
        ld_addr[0] = b0;
        ld_addr[1] = b1;
    }

    const float4* x4 = reinterpret_cast<const float4*>(x + (size_t)b * Tv);
    float4 nx = x4[0];                         // double-buffered x (4 steps/load)

    // ---- 3-phase stagger: warps {s, s+4, s+8} share an SMSP; delay by
    // (warp>>2) * ~1/3 step via a dependent FMA chain.
    {
        const int reps = (warp >> 2) * 20;     // 0 / 20 / 40 dependent FFMA
        float d = 1.0f + (float)lane;
        for (int it = 0; it < reps; it++) d = fmaf(d, 1.0000001f, 1.0f);
        if (d == -1.0f) out[0] = d;            // never true; keeps the chain
    }

    // ---- Pipelined seeds for step 0.
    uint32_t aif, ago;
    {
        const uint32_t xh2 = pack_h2(nx.x, nx.x);
        aif = hfma2(xh2, wih16_if, bias16_if);
        ago = hfma2(xh2, wih16_go, bias16_go);
    }

    for (int t0 = 0; t0 < Tv; t0 += 4) {
        const float4 cur = nx;
        const int nxt = (t0 >> 2) + 1;
        if (nxt < Tv / 4) nx = x4[nxt];

#pragma unroll
        for (int u = 0; u < 4; u++) {
            // 2 packed 10-deep f16x2 chains (i,f) and (g,o); aif/ago carry the
            // pre-computed seed (x*W_ih + b).
#pragma unroll
            for (int k = 0; k < 10; k++) {
                aif = hfma2(h2d[k], wif16[k], aif);
                ago = hfma2(h2d[k], wgo16[k], ago);
            }

            // Packed activations + packed c-path front end.
            const uint32_t tif = tanh2_h(aif);   // {ti, tf}
            const uint32_t tgo = tanh2_h(ago);   // {tg, to}
            const uint32_t s2  = hfma2(half2_16, tif, half2_16); // {i, f}
            const uint32_t m2  = hmul2(s2, tgo);                 // {i*g, junk}

            const float ig = cvt_lo(m2);
            const float fv = cvt_hi(s2);
            const float to = cvt_hi(tgo);

            // fp32 tail: c = f*c + i*g, h' = to*tc + tc.
            c = fmaf(fv, c, ig);
            const float tc = tanh_a(c);
            hown = fmaf(to, tc, tc);             // h' = 2h

            // Exchange (no syncwarp: convergent warp, in-order per-warp LSU).
            const int par = u & 1;
            const uint32_t hd = pack_h2(hown, hown);
            sts32(st_addr[par], hd);

            // Seeds for the NEXT step fill the store->load window.
            {
                const float xt_n = (u == 0) ? cur.y : (u == 1) ? cur.z
                                 : (u == 2) ? cur.w : nx.x;
                const uint32_t xh2 = pack_h2(xt_n, xt_n);
                aif = hfma2(xh2, wih16_if, bias16_if);
                ago = hfma2(xh2, wih16_go, bias16_go);
            }

            lds128(ld_addr[par],      h2d[0], h2d[1], h2d[2], h2d[3]);
            lds128(ld_addr[par] + 16, h2d[4], h2d[5], h2d[6], h2d[7]);
            lds64 (ld_addr[par] + 32, h2d[8], h2d[9]);
        }
    }

    // ---- Epilogue: out[b] = h . W_out + b_out, with h = 0.5*h'.
    const float p = hown * (W_out[j] * 0.5f);
    float sum = 0.f;
#pragma unroll
    for (int k = 0; k < 10; k++) {
        sum += __shfl_sync(FULL_MASK, p, base + k);
    }
    if (active && j == 0) {
        out[b] = sum + b_out[0];
    }
}

extern "C" void kernel_launch(void* const* d_in, const int* in_sizes, int n_in,
                              void* d_out, int out_size) {
    (void)in_sizes; (void)n_in; (void)out_size;
    const float* x     = (const float*)d_in[0];
    const float* W_ih  = (const float*)d_in[1];
    const float* W_hh  = (const float*)d_in[2];
    const float* b_ih  = (const float*)d_in[3];
    const float* b_hh  = (const float*)d_in[4];
    const float* W_out = (const float*)d_in[5];
    const float* b_out = (const float*)d_in[6];
    float* out = (float*)d_out;

    lstm_kernel<<<NBLOCKS, THREADS>>>(x, W_ih, W_hh, b_ih, b_hh, W_out, b_out, out);
}